// round 11
// baseline (speedup 1.0000x reference)
#include <cuda_runtime.h>
#include <cuda_bf16.h>

// BPMLL loss, factorized:
//   inner[b]  = (sum_{t==0} exp(x)) * (sum_{t==1} exp(-x))
//   length[b] = n_pos * n_neg
//   out       = sum_b inner[b] / length[b]
//
// B = 128, L = 1024, target int32 (values exactly 0/1).
//
// R11 = R8 (proven best: one warp per row, 128 x 32, no BAR/smem, single
// packed u64 atomic finish) with a shorter per-element path:
//   - sign flip via bit XOR:  exp(t? -v : v) = ex2(asfloat(asuint(v) ^ (t<<31)) * log2e)
//   - total/pos accumulation: s_tot += e; s_pos += ft*e (ft = t as float via IMAD)
//     -> s_neg = s_tot - s_pos after the warp reduce.
// Finish: single u64 fixed-point atomic (low 56 bits = 2^32 fixed-point loss
// sum, high 8 bits = arrival counter) -> bit-deterministic across replays.

__device__ unsigned long long g_acc = 0ULL;

#define CNT_ONE   (1ULL << 56)
#define VAL_MASK  (CNT_ONE - 1ULL)
#define FP_SCALE  4294967296.0   // 2^32

__device__ __forceinline__ float ex2_approx(float x) {
    float r;
    asm("ex2.approx.f32 %0, %1;" : "=f"(r) : "f"(x));
    return r;
}

__global__ void __launch_bounds__(32, 1)
bpmll_warp_kernel(const float* __restrict__ inp,
                  const int* __restrict__ tgt,
                  float* __restrict__ out,
                  int L, int B) {
    const int b   = blockIdx.x;
    const int lid = threadIdx.x;   // 0..31
    const float4* __restrict__ x4 = (const float4*)(inp + (size_t)b * L);
    const int4*   __restrict__ t4 = (const int4*)(tgt + (size_t)b * L);

    // L=1024 -> 256 float4 per row -> 8 per lane. Front-batch all loads
    // (16 outstanding LDG.128 per lane for max MLP).
    float4 v[8];
    int4   t[8];
    #pragma unroll
    for (int k = 0; k < 8; ++k) {
        v[k] = x4[lid + 32 * k];
        t[k] = t4[lid + 32 * k];
    }

    const float L2E = 1.4426950408889634f;   // log2(e)

    float s_tot = 0.0f;    // sum over all elements of exp(sgn * x)
    float s_pos = 0.0f;    // same sum restricted to positives (t==1)
    unsigned int np = 0u;  // positives count

    #pragma unroll
    for (int k = 0; k < 8; ++k) {
        #define ACCUM(vv, tt)                                                  \
        {                                                                      \
            unsigned int ti = (unsigned int)(tt);                              \
            /* flip sign iff positive: exp(-x) for t==1, exp(x) for t==0 */    \
            float xs = __uint_as_float(__float_as_uint(vv) ^ (ti << 31));      \
            float e  = ex2_approx(xs * L2E);                                   \
            float ft = __uint_as_float(ti * 0x3F800000u);  /* 0.0f or 1.0f */  \
            s_tot += e;                                                        \
            s_pos  = fmaf(ft, e, s_pos);                                       \
            np    += ti;                                                       \
        }
        ACCUM(v[k].x, t[k].x)
        ACCUM(v[k].y, t[k].y)
        ACCUM(v[k].z, t[k].z)
        ACCUM(v[k].w, t[k].w)
        #undef ACCUM
    }

    // n_pos: single-instruction integer warp reduction
    np = __reduce_add_sync(0xffffffffu, np);

    // interleaved f32 shfl-xor chains
    #pragma unroll
    for (int off = 16; off > 0; off >>= 1) {
        s_tot += __shfl_xor_sync(0xffffffffu, s_tot, off);
        s_pos += __shfl_xor_sync(0xffffffffu, s_pos, off);
    }

    if (lid == 0) {
        float s_neg = s_tot - s_pos;       // sum exp(x) over negatives
        float fnp = (float)np;
        float fnn = (float)L - fnp;
        float loss = (s_neg * s_pos) / (fnp * fnn);

        unsigned long long myval =
            (unsigned long long)llrint((double)loss * FP_SCALE) + CNT_ONE;
        unsigned long long old = atomicAdd(&g_acc, myval);

        if ((old >> 56) == (unsigned long long)(B - 1)) {
            unsigned long long total = (old + myval) & VAL_MASK;
            out[0] = (float)((double)total * (1.0 / FP_SCALE));
            g_acc = 0ULL;   // reset for next graph replay
        }
    }
}

extern "C" void kernel_launch(void* const* d_in, const int* in_sizes, int n_in,
                              void* d_out, int out_size) {
    const float* inp = (const float*)d_in[0];
    const int*   tgt = (const int*)d_in[1];
    float* out = (float*)d_out;

    const int B = 128;
    const int L = in_sizes[0] / B;   // 1024

    bpmll_warp_kernel<<<B, 32>>>(inp, tgt, out, L, B);
}

// round 12
// speedup vs baseline: 1.0386x; 1.0386x over previous
#include <cuda_runtime.h>
#include <cuda_bf16.h>

// BPMLL loss, factorized:
//   inner[b]  = (sum_{t==0} exp(x)) * (sum_{t==1} exp(-x))
//   length[b] = n_pos * n_neg
//   out       = sum_b inner[b] / length[b]
//
// B = 128, L = 1024, target int32.
//
// FINAL (= R8, campaign best: ncu 5.06us, dur 6.59us): one warp per row,
// grid = 128 x 32 (one warp per SM, single wave). Each lane front-batches
// 8 x (float4 + int4) loads (16 outstanding LDG.128 -> full MLP), float
// exp-sums with branchless __expf, integer n_pos (targets are 0/1). Reduce =
// two interleaved f32 shfl chains + one REDUX.SUM.U32. No __syncthreads,
// no smem. Finish: single u64 fixed-point atomic per row (low 56 bits =
// 2^32 fixed-point loss sum, high 8 bits = arrival counter) -> last arriver
// reads the total from the atomic return value. Integer adds everywhere ->
// bit-deterministic across graph replays (rel_err 0.0 observed).
//
// Perf model (validated over 11 rounds): ~4.5us fixed launch/ramp overhead
// + ~0.5us work; DRAM/pipes <3% busy. Overhead-bound; structural variants
// (block shapes, atomic spreading, fences, op trims) all land within noise.

__device__ unsigned long long g_acc = 0ULL;

#define CNT_ONE   (1ULL << 56)
#define VAL_MASK  (CNT_ONE - 1ULL)
#define FP_SCALE  4294967296.0   // 2^32

__global__ void __launch_bounds__(32, 1)
bpmll_warp_kernel(const float* __restrict__ inp,
                  const int* __restrict__ tgt,
                  float* __restrict__ out,
                  int L, int B) {
    const int b   = blockIdx.x;
    const int lid = threadIdx.x;   // 0..31
    const float4* __restrict__ x4 = (const float4*)(inp + (size_t)b * L);
    const int4*   __restrict__ t4 = (const int4*)(tgt + (size_t)b * L);

    // L=1024 -> 256 float4 per row -> 8 per lane. Front-batch all loads.
    float4 v[8];
    int4   t[8];
    #pragma unroll
    for (int k = 0; k < 8; ++k) {
        v[k] = x4[lid + 32 * k];
        t[k] = t4[lid + 32 * k];
    }

    float s_neg  = 0.0f;   // sum exp(x) over negatives
    float s_pinv = 0.0f;   // sum exp(-x) over positives
    unsigned int np = 0u;  // positives count (targets are 0/1)

    #pragma unroll
    for (int k = 0; k < 8; ++k) {
        {
            bool p = (t[k].x == 1); float e = __expf(p ? -v[k].x : v[k].x);
            s_pinv += p ? e : 0.0f; s_neg += p ? 0.0f : e; np += (unsigned)t[k].x;
        }
        {
            bool p = (t[k].y == 1); float e = __expf(p ? -v[k].y : v[k].y);
            s_pinv += p ? e : 0.0f; s_neg += p ? 0.0f : e; np += (unsigned)t[k].y;
        }
        {
            bool p = (t[k].z == 1); float e = __expf(p ? -v[k].z : v[k].z);
            s_pinv += p ? e : 0.0f; s_neg += p ? 0.0f : e; np += (unsigned)t[k].z;
        }
        {
            bool p = (t[k].w == 1); float e = __expf(p ? -v[k].w : v[k].w);
            s_pinv += p ? e : 0.0f; s_neg += p ? 0.0f : e; np += (unsigned)t[k].w;
        }
    }

    // n_pos: single-instruction integer warp reduction
    np = __reduce_add_sync(0xffffffffu, np);

    // two interleaved f32 shfl-xor chains
    #pragma unroll
    for (int off = 16; off > 0; off >>= 1) {
        s_neg  += __shfl_xor_sync(0xffffffffu, s_neg,  off);
        s_pinv += __shfl_xor_sync(0xffffffffu, s_pinv, off);
    }

    if (lid == 0) {
        float fnp = (float)np;
        float fnn = (float)L - fnp;
        float loss = (s_neg * s_pinv) / (fnp * fnn);

        unsigned long long myval =
            (unsigned long long)llrint((double)loss * FP_SCALE) + CNT_ONE;
        unsigned long long old = atomicAdd(&g_acc, myval);

        if ((old >> 56) == (unsigned long long)(B - 1)) {
            unsigned long long total = (old + myval) & VAL_MASK;
            out[0] = (float)((double)total * (1.0 / FP_SCALE));
            g_acc = 0ULL;   // reset for next graph replay
        }
    }
}

extern "C" void kernel_launch(void* const* d_in, const int* in_sizes, int n_in,
                              void* d_out, int out_size) {
    const float* inp = (const float*)d_in[0];
    const int*   tgt = (const int*)d_in[1];
    float* out = (float*)d_out;

    const int B = 128;
    const int L = in_sizes[0] / B;   // 1024

    bpmll_warp_kernel<<<B, 32>>>(inp, tgt, out, L, B);
}